// round 14
// baseline (speedup 1.0000x reference)
#include <cuda_runtime.h>
#include <math.h>
#include <stdint.h>

#define NB 512
#define NC 151
#define IN_DIM 4096
#define NMS_T 0.3f
#define FULL 0xffffffffu

#define KS 32            // k-splits
#define BKS (IN_DIM/KS)  // 128
#define BN 160           // padded N

// ---- device scratch (no allocations allowed) ----
__device__ float    g_part[KS * NB * BN];        // split-K partials
__device__ float    g_scores_rm[NB * NC];        // row-major softmax scores
__device__ unsigned g_masks16[NC * NB * 16];     // [c][box][w]: bit l of w = overlap(32w+l, box)
__device__ __align__(16) float g_t4val[NB * 4];  // per-row top-4 values (desc, cls asc)
__device__ int      g_t4cls[NB * 4];

// monotonic-uint mapping for float compare (handles the -1 sentinel)
__device__ __forceinline__ unsigned fmono(float v) {
    unsigned b = __float_as_uint(v);
    return (b & 0x80000000u) ? ~b : (b | 0x80000000u);
}
__device__ __forceinline__ float fmono_inv_u(unsigned u) {
    return (u & 0x80000000u) ? __uint_as_float(u ^ 0x80000000u) : __uint_as_float(~u);
}

// =================== fused: GEMM split-K partials + symmetric IoU masks ===================
__global__ void __launch_bounds__(256) fused_gemm_mask(
    const float* __restrict__ A, const float* __restrict__ W,
    const float* __restrict__ boxes)
{
    __shared__ union {
        struct { float As[8][65]; float Bs[8][BN]; } g;
        struct { float4 box[NB]; float area[NB]; } m;
    } sm;
    const int tid = threadIdx.x;

    if (blockIdx.x < NC) {
        // ---------------- mask path: one class per block, symmetric tiles ----------------
        const int c = blockIdx.x;
        const int lane = tid & 31, w = tid >> 5;
        for (int i = tid; i < NB; i += 256) {
            float4 v = ((const float4*)boxes)[i * NC + c];
            float bw = __fadd_rn(__fsub_rn(v.z, v.x), 1.0f);
            float bh = __fadd_rn(__fsub_rn(v.w, v.y), 1.0f);
            sm.m.box[i] = v;
            sm.m.area[i] = __fmul_rn(bw, bh);
        }
        __syncthreads();

        unsigned* gb = &g_masks16[(size_t)c * NB * 16];
        int tcnt = 0;
        for (int pb = 0; pb < 16; pb++) {
            for (int jb = pb; jb < 16; jb++, tcnt++) {
                if ((tcnt & 7) != w) continue;
                const int p = (pb << 5) + lane;
                const float4 pv = sm.m.box[p];
                const float par = sm.m.area[p];
                unsigned bword = 0, tmask = 0;
                for (int jj = 0; jj < 32; jj++) {
                    int j = (jb << 5) + jj;
                    float4 bv = sm.m.box[j];
                    float baj = sm.m.area[j];
                    float ix1 = fmaxf(pv.x, bv.x);
                    float iy1 = fmaxf(pv.y, bv.y);
                    float ix2 = fminf(pv.z, bv.z);
                    float iy2 = fminf(pv.w, bv.w);
                    float iw = fmaxf(__fadd_rn(__fsub_rn(ix2, ix1), 1.0f), 0.0f);
                    float ih = fmaxf(__fadd_rn(__fsub_rn(iy2, iy1), 1.0f), 0.0f);
                    float inter = __fmul_rn(iw, ih);
                    float uni = __fsub_rn(__fadd_rn(par, baj), inter);
                    float t3 = __fmul_rn(NMS_T, uni);
                    float diff = inter - t3;
                    bool pred = diff > 0.0f;
                    bool near = fabsf(diff) <= 1e-4f * t3;
                    if (__any_sync(FULL, near)) {
                        float q = __fdiv_rn(inter, uni);
                        if (near) pred = (q >= NMS_T);
                    }
                    unsigned word = __ballot_sync(FULL, pred);
                    if (lane == jj) bword = word;
                    tmask |= ((unsigned)pred) << jj;
                }
                gb[(((jb << 5) + lane) << 4) + pb] = bword;     // boxes in jb, pivot-bits pb
                if (jb != pb)
                    gb[(((pb << 5) + lane) << 4) + jb] = tmask; // boxes in pb, j-bits jb (symmetry)
            }
        }
    } else {
        // ---------------- gemm path (identical numerics) ----------------
        const int bi = blockIdx.x - NC;
        const int mt = bi >> 5;          // 0..7
        const int ks = bi & 31;          // 0..31
        const int tx = tid & 15, ty = tid >> 4;
        const int k0 = ks * BKS;

        float acc[4][10];
#pragma unroll
        for (int i = 0; i < 4; i++)
#pragma unroll
            for (int j = 0; j < 10; j++) acc[i][j] = 0.0f;

        for (int kc = 0; kc < BKS; kc += 8) {
#pragma unroll
            for (int r = 0; r < 2; r++) {
                int idx = tid + r * 256;
                int m = idx >> 3, kk = idx & 7;
                sm.g.As[kk][m] = A[(mt * 64 + m) * IN_DIM + k0 + kc + kk];
            }
#pragma unroll
            for (int r = 0; r < 5; r++) {
                int idx = tid + r * 256;
                int kk = idx / BN, n = idx % BN;
                sm.g.Bs[kk][n] = (n < NC) ? W[(k0 + kc + kk) * NC + n] : 0.0f;
            }
            __syncthreads();
#pragma unroll
            for (int kk = 0; kk < 8; kk++) {
                float a[4], b[10];
#pragma unroll
                for (int i = 0; i < 4; i++) a[i] = sm.g.As[kk][ty * 4 + i];
#pragma unroll
                for (int j = 0; j < 10; j++) b[j] = sm.g.Bs[kk][tx * 10 + j];
#pragma unroll
                for (int i = 0; i < 4; i++)
#pragma unroll
                    for (int j = 0; j < 10; j++) acc[i][j] = fmaf(a[i], b[j], acc[i][j]);
            }
            __syncthreads();
        }
#pragma unroll
        for (int i = 0; i < 4; i++) {
            int m = mt * 64 + ty * 4 + i;
#pragma unroll
            for (int j = 0; j < 10; j++) {
                int n = tx * 10 + j;
                g_part[(ks * NB + m) * BN + n] = acc[i][j];
            }
        }
    }
}

// =================== reduce + bias + softmax + exact top-4 ===================
__global__ void __launch_bounds__(256) softmax_kernel(const float* __restrict__ bias,
                                                      float* __restrict__ out)
{
    const int b = blockIdx.x;
    const int t = threadIdx.x;
    __shared__ float sred[256];
    __shared__ int   sidx[256];
    __shared__ int   s_win;

    float d = -INFINITY;
    if (t < NC) {
        float s = 0.0f;
#pragma unroll 8
        for (int ks = 0; ks < KS; ks++) s += g_part[(ks * NB + b) * BN + t];
        d = s + bias[t];
        out[b * NC + t] = d;
    }
    sred[t] = d;
    __syncthreads();
    for (int off = 128; off; off >>= 1) {
        if (t < off) sred[t] = fmaxf(sred[t], sred[t + off]);
        __syncthreads();
    }
    float m = sred[0];
    __syncthreads();

    float e = (t < NC) ? expf(__fsub_rn(d, m)) : 0.0f;
    sred[t] = e;
    __syncthreads();
    for (int off = 128; off; off >>= 1) {
        if (t < off) sred[t] = __fadd_rn(sred[t], sred[t + off]);
        __syncthreads();
    }
    float s = sred[0];
    __syncthreads();

    float sc = -INFINITY;
    if (t < NC) {
        sc = (t == 0) ? 0.0f : __fdiv_rn(e, s);
        g_scores_rm[b * NC + t] = sc;
    }

    // 4 argmax passes: (val desc, cls asc) with exclusion
    bool excl = false;
#pragma unroll
    for (int p = 0; p < 4; p++) {
        sred[t] = excl ? -INFINITY : sc;
        sidx[t] = t;
        __syncthreads();
        for (int off = 128; off; off >>= 1) {
            if (t < off) {
                float ov = sred[t + off]; int oi = sidx[t + off];
                if (ov > sred[t] || (ov == sred[t] && oi < sidx[t])) { sred[t] = ov; sidx[t] = oi; }
            }
            __syncthreads();
        }
        if (t == 0) {
            g_t4val[b * 4 + p] = sred[0];
            g_t4cls[b * 4 + p] = sidx[0];
            s_win = sidx[0];
        }
        __syncthreads();
        if (t == s_win) excl = true;
        __syncthreads();
    }
}

// =================== sequential greedy NMS (single warp, 3-wide pipelined update) ===================
__global__ void __launch_bounds__(32, 1) nms_kernel(float* __restrict__ out)
{
    __shared__ short rarg[NB];
    __shared__ __align__(16) float t4v[NB * 4];
    __shared__ __align__(8)  short t4c[NB * 4];
    __shared__ unsigned zb[NB * 5];
    __shared__ short commits[NB];
    __shared__ short marked[NB];
    __shared__ int s_nm;

    const int l = threadIdx.x;
    float v[16];                       // register-resident rmax of owned rows
    unsigned retm = 0, resm = 0;       // per-lane retired / resurrected bitmasks
    unsigned long long vbq = 0xFFFFFFFFFFFFFFFFull;   // 16 x 4-bit top-4 validity

    // ---- init (each lane its own 16 rows) ----
#pragma unroll
    for (int k = 0; k < 16; k++) {
        int r = (l << 4) + k;
        float4 tv = *(const float4*)&g_t4val[r * 4];
        t4v[r * 4 + 0] = tv.x; t4v[r * 4 + 1] = tv.y;
        t4v[r * 4 + 2] = tv.z; t4v[r * 4 + 3] = tv.w;
        int4 tc = *(const int4*)&g_t4cls[r * 4];
        t4c[r * 4 + 0] = (short)tc.x; t4c[r * 4 + 1] = (short)tc.y;
        t4c[r * 4 + 2] = (short)tc.z; t4c[r * 4 + 3] = (short)tc.w;
        v[k] = tv.x;
        rarg[r] = (short)tc.x;
        commits[r] = 0;
#pragma unroll
        for (int q = 0; q < 5; q++) zb[r * 5 + q] = 0;
    }
    if (l == 0) s_nm = 0;
    __syncwarp();

    // ---- plain register argmax (all-lane, branchless; ties -> lowest row) ----
    auto warp_argmax = [&](int& obox, bool& pos) {
        float a0 = fmaxf(v[0], v[1]),   a1 = fmaxf(v[2], v[3]);
        float a2 = fmaxf(v[4], v[5]),   a3 = fmaxf(v[6], v[7]);
        float a4 = fmaxf(v[8], v[9]),   a5 = fmaxf(v[10], v[11]);
        float a6 = fmaxf(v[12], v[13]), a7 = fmaxf(v[14], v[15]);
        float b0 = fmaxf(a0, a1), b1 = fmaxf(a2, a3);
        float b2 = fmaxf(a4, a5), b3 = fmaxf(a6, a7);
        float c0 = fmaxf(b0, b1), c1 = fmaxf(b2, b3);
        float bm = fmaxf(c0, c1);
        unsigned g0 = (v[0]==bm ? 1u:0u) | (v[1]==bm ? 2u:0u) | (v[2]==bm ? 4u:0u) | (v[3]==bm ? 8u:0u);
        unsigned g1 = (v[4]==bm ? 1u:0u) | (v[5]==bm ? 2u:0u) | (v[6]==bm ? 4u:0u) | (v[7]==bm ? 8u:0u);
        unsigned g2 = (v[8]==bm ? 1u:0u) | (v[9]==bm ? 2u:0u) | (v[10]==bm ? 4u:0u) | (v[11]==bm ? 8u:0u);
        unsigned g3 = (v[12]==bm ? 1u:0u) | (v[13]==bm ? 2u:0u) | (v[14]==bm ? 4u:0u) | (v[15]==bm ? 8u:0u);
        unsigned eqm = g0 | (g1 << 4) | (g2 << 8) | (g3 << 12);
        int idx = __ffs(eqm) - 1;
        unsigned m1 = fmono(bm);
        unsigned gm = __reduce_max_sync(FULL, m1);
        unsigned bal = __ballot_sync(FULL, m1 == gm);
        int wl = __ffs(bal) - 1;
        obox = __shfl_sync(FULL, (l << 4) + idx, wl);
        pos = gm > 0x80000000u;        // value strictly > 0
    };

    // ---- single-hit processing (remainder path; same semantics) ----
    auto process = [&](unsigned& hits, int cls, int cwi, unsigned cbm) {
        bool has = hits != 0;
        int i = has ? (__ffs(hits) - 1) : 0;
        hits &= hits - 1;
        int r = (l << 4) + i;
        unsigned zw = zb[r * 5 + cwi];
        bool firstz = has && !(zw & cbm);
        bool ret = (retm >> i) & 1u;
        bool res = (resm >> i) & 1u;
        short ra = rarg[r];
        bool act_ret = firstz && ret;
        short nra_ret = (!res) ? (short)cls : ((cls < (int)ra) ? (short)cls : ra);
        bool livez = firstz && !ret && (cls != 0);
        uint2 cp = *(const uint2*)&t4c[r * 4];
        short c0 = (short)(cp.x & 0xFFFF), c1s = (short)(cp.x >> 16);
        short c2 = (short)(cp.y & 0xFFFF), c3 = (short)(cp.y >> 16);
        int k4 = -1;
        k4 = ((int)c3 == cls) ? 3 : k4;
        k4 = ((int)c2 == cls) ? 2 : k4;
        k4 = ((int)c1s == cls) ? 1 : k4;
        k4 = ((int)c0 == cls) ? 0 : k4;
        unsigned vbm = (unsigned)(vbq >> (i * 4)) & 0xFu;
        bool inv = livez && (k4 >= 0) && ((vbm >> (k4 & 3)) & 1u);
        unsigned vbm2 = vbm & ~(1u << (k4 & 3));
        int h = __ffs(vbm2) - 1; int hh = (h < 0) ? 0 : h;
        float4 tv4 = *(const float4*)&t4v[r * 4];
        float nrm_live = (hh == 0) ? tv4.x : (hh == 1) ? tv4.y : (hh == 2) ? tv4.z : tv4.w;
        short nra_live = (hh == 0) ? c0 : (hh == 1) ? c1s : (hh == 2) ? c2 : c3;
        bool promote = inv && (vbm2 != 0);
        bool mark = inv && (vbm2 == 0);
        if (act_ret || livez) zb[r * 5 + cwi] = zw | cbm;
        if (act_ret) resm |= 1u << i;
        if (inv) vbq = (vbq & ~(0xFull << (i * 4))) | ((unsigned long long)vbm2 << (i * 4));
        bool wr = act_ret || promote;
        float nv = act_ret ? 0.0f : nrm_live;
        short na = act_ret ? nra_ret : nra_live;
        if (wr) rarg[r] = na;
#pragma unroll
        for (int k = 0; k < 16; k++) v[k] = (wr && k == i) ? nv : v[k];
        if (mark) marked[atomicAdd(&s_nm, 1)] = (short)r;
    };

    // ---- prologue ----
    int box; bool pos0;
    warp_argmax(box, pos0);
    int cls = (int)rarg[box];
    unsigned word = __ldg(&g_masks16[(((size_t)cls * NB) + box) * 16 + (l >> 1)]);

    for (int iter = 0; iter < NB; iter++) {
        if (l == 0) commits[box] = (short)cls;
        const int owner = box >> 4;

        // ---- retire pivot FIRST (owner lane only) ----
        {
            int bi = box & 15;
            bool own = (l == owner);
            if (own) {
                retm |= 1u << bi;
                resm &= ~(1u << bi);
                vbq &= ~(0xFull << (bi * 4));
                rarg[box] = 0;
#pragma unroll
                for (int q = 0; q < 5; q++) zb[box * 5 + q] = 0;
            }
#pragma unroll
            for (int k = 0; k < 16; k++) v[k] = (own && k == bi) ? -1.0f : v[k];
        }

        // ---- exact lookahead: plain argmax (pivot already -1) ----
        int sbox; bool svalid;
        warp_argmax(sbox, svalid);
        int scls = (int)rarg[sbox];
        unsigned sword = __ldg(&g_masks16[(((size_t)scls * NB) + sbox) * 16 + (l >> 1)]);
        unsigned wsb = __shfl_sync(FULL, word, (sbox >> 5) << 1);
        bool sbox_hit = (wsb >> (sbox & 31)) & 1u;

        // ---- update phase: 3-wide ILP peel, then rare remainder ----
        const int cwi = cls >> 5;
        const unsigned cbm = 1u << (cls & 31);
        unsigned hits = (word >> ((l & 1) * 16)) & 0xFFFFu;
        if (l == owner) hits &= ~(1u << (box & 15));
        {
            // extract up to 3 hit rows with distinct registers
            bool hA[3]; int iA[3];
#pragma unroll
            for (int j = 0; j < 3; j++) {
                hA[j] = hits != 0;
                iA[j] = hA[j] ? (__ffs(hits) - 1) : 0;
                hits &= hits - 1;
            }
            // issue ALL loads up front (MLP)
            unsigned zwA[3]; uint2 cpA[3]; short raA[3]; float4 tvA[3];
#pragma unroll
            for (int j = 0; j < 3; j++) {
                int r = (l << 4) + iA[j];
                zwA[j] = zb[r * 5 + cwi];
                cpA[j] = *(const uint2*)&t4c[r * 4];
                raA[j] = rarg[r];
                tvA[j] = *(const float4*)&t4v[r * 4];
            }
            // compute + predicated commits (rows distinct -> independent)
#pragma unroll
            for (int j = 0; j < 3; j++) {
                int i = iA[j];
                int r = (l << 4) + i;
                bool firstz = hA[j] && !(zwA[j] & cbm);
                bool ret = (retm >> i) & 1u;
                bool res = (resm >> i) & 1u;
                bool act_ret = firstz && ret;
                short nra_ret = (!res) ? (short)cls : ((cls < (int)raA[j]) ? (short)cls : raA[j]);
                bool livez = firstz && !ret && (cls != 0);
                short c0 = (short)(cpA[j].x & 0xFFFF), c1s = (short)(cpA[j].x >> 16);
                short c2 = (short)(cpA[j].y & 0xFFFF), c3 = (short)(cpA[j].y >> 16);
                int k4 = -1;
                k4 = ((int)c3 == cls) ? 3 : k4;
                k4 = ((int)c2 == cls) ? 2 : k4;
                k4 = ((int)c1s == cls) ? 1 : k4;
                k4 = ((int)c0 == cls) ? 0 : k4;
                unsigned vbm = (unsigned)(vbq >> (i * 4)) & 0xFu;
                bool inv = livez && (k4 >= 0) && ((vbm >> (k4 & 3)) & 1u);
                unsigned vbm2 = vbm & ~(1u << (k4 & 3));
                int h = __ffs(vbm2) - 1; int hh = (h < 0) ? 0 : h;
                float nrm_live = (hh == 0) ? tvA[j].x : (hh == 1) ? tvA[j].y : (hh == 2) ? tvA[j].z : tvA[j].w;
                short nra_live = (hh == 0) ? c0 : (hh == 1) ? c1s : (hh == 2) ? c2 : c3;
                bool promote = inv && (vbm2 != 0);
                bool mark = inv && (vbm2 == 0);
                if (act_ret || livez) zb[r * 5 + cwi] = zwA[j] | cbm;
                if (act_ret) resm |= 1u << i;
                if (inv) vbq = (vbq & ~(0xFull << (i * 4))) | ((unsigned long long)vbm2 << (i * 4));
                bool wr = act_ret || promote;
                float nv = act_ret ? 0.0f : nrm_live;
                short na = act_ret ? nra_ret : nra_live;
                if (wr) rarg[r] = na;
#pragma unroll
                for (int k = 0; k < 16; k++) v[k] = (wr && k == i) ? nv : v[k];
                if (mark) marked[atomicAdd(&s_nm, 1)] = (short)r;
            }
        }
        while (__any_sync(FULL, hits))                // rare remainder (>3 hits in a lane)
            process(hits, cls, cwi, cbm);
        __syncwarp();

        // ---- rescans (rare): refill top-4 of marked rows ----
        int nm = s_nm;
        if (nm) {
            for (int i = 0; i < nm; i++) {
                int r = (int)marked[i];
                float ev[5];
#pragma unroll
                for (int j = 0; j < 5; j++) {
                    int c = l + 32 * j;
                    float sv = -1e30f;
                    if (c < NC) {
                        sv = __ldg(&g_scores_rm[r * NC + c]);
                        if (c == 0 || ((zb[r * 5 + (c >> 5)] >> (c & 31)) & 1u)) sv = 0.0f;
                    }
                    ev[j] = sv;
                }
                unsigned taken = 0;
                float wv0 = 0.0f; int wc0 = 0;
#pragma unroll
                for (int p = 0; p < 4; p++) {
                    float bv = -1e30f; int bj = -1;
#pragma unroll
                    for (int j = 0; j < 5; j++) {
                        bool can = !((taken >> j) & 1u) && (l + 32 * j < NC);
                        if (can && ev[j] > bv) { bv = ev[j]; bj = j; }
                    }
                    unsigned key = (bj >= 0) ? fmono(bv) : 0u;
                    unsigned gmx = __reduce_max_sync(FULL, key);
                    unsigned candc = (key == gmx && bj >= 0) ? (unsigned)(l + 32 * bj) : 0xFFFFFFFFu;
                    unsigned wc = __reduce_min_sync(FULL, candc);
                    float wv = fmono_inv_u(gmx);
                    if (l == (int)(wc & 31)) taken |= 1u << (wc >> 5);
                    if (l == 0) { t4v[r * 4 + p] = wv; t4c[r * 4 + p] = (short)wc; }
                    if (p == 0) { wv0 = wv; wc0 = (int)wc; }
                }
                if (l == 0) rarg[r] = (short)wc0;
                {
                    int ro = r >> 4, ri = r & 15;
                    bool own = (l == ro);
                    if (own) vbq |= 0xFull << (ri * 4);
#pragma unroll
                    for (int k = 0; k < 16; k++) v[k] = (own && k == ri) ? wv0 : v[k];
                }
            }
            if (l == 0) s_nm = 0;
            __syncwarp();
        }

        // ---- advance ----
        if (svalid && !sbox_hit) {
            box = sbox; cls = scls; word = sword;
        } else {
            bool p2;
            warp_argmax(box, p2);
            cls = (int)rarg[box];
            word = __ldg(&g_masks16[(((size_t)cls * NB) + box) * 16 + (l >> 1)]);
        }
    }

    for (int i = l; i < NB; i += 32) out[NB * NC + i] = (float)commits[i];
}

// =================== launch ===================
extern "C" void kernel_launch(void* const* d_in, const int* in_sizes, int n_in,
                              void* d_out, int out_size) {
    const float* obj_fmap = (const float*)d_in[0];   // [512,4096]
    const float* boxes    = (const float*)d_in[1];   // [512,151,4]
    const float* W        = (const float*)d_in[2];   // [4096,151]
    const float* b        = (const float*)d_in[3];   // [151]
    float* out = (float*)d_out;                      // 77312 dists + 512 preds

    fused_gemm_mask<<<NC + 256, 256>>>(obj_fmap, W, boxes);
    softmax_kernel<<<NB, 256>>>(b, out);
    nms_kernel<<<1, 32>>>(out);
}

// round 15
// speedup vs baseline: 1.0199x; 1.0199x over previous
#include <cuda_runtime.h>
#include <math.h>
#include <stdint.h>

#define NB 512
#define NC 151
#define IN_DIM 4096
#define NMS_T 0.3f
#define FULL 0xffffffffu

#define KS 32            // k-splits
#define BKS (IN_DIM/KS)  // 128
#define BN 160           // padded N

// ---- device scratch (no allocations allowed) ----
__device__ float    g_part[KS * NB * BN];        // split-K partials
__device__ float    g_scores_rm[NB * NC];        // row-major softmax scores
__device__ unsigned g_masks16[NC * NB * 16];     // [c][box][w]: bit l of w = overlap(32w+l, box)
__device__ __align__(16) float g_t4val[NB * 4];  // per-row top-4 values (desc, cls asc)
__device__ int      g_t4cls[NB * 4];

// monotonic-uint mapping for float compare (handles the -1 sentinel)
__device__ __forceinline__ unsigned fmono(float v) {
    unsigned b = __float_as_uint(v);
    return (b & 0x80000000u) ? ~b : (b | 0x80000000u);
}
__device__ __forceinline__ float fmono_inv_u(unsigned u) {
    return (u & 0x80000000u) ? __uint_as_float(u ^ 0x80000000u) : __uint_as_float(~u);
}

// =================== fused: GEMM split-K partials + symmetric IoU masks ===================
// GEMM path slimmed to acc[2][10] (32-row m-tiles) to cut regs -> higher occupancy.
__global__ void __launch_bounds__(256) fused_gemm_mask(
    const float* __restrict__ A, const float* __restrict__ W,
    const float* __restrict__ boxes)
{
    __shared__ union {
        struct { float As[8][33]; float Bs[8][BN]; } g;
        struct { float4 box[NB]; float area[NB]; } m;
    } sm;
    const int tid = threadIdx.x;

    if (blockIdx.x < NC) {
        // ---------------- mask path: one class per block, symmetric tiles ----------------
        const int c = blockIdx.x;
        const int lane = tid & 31, w = tid >> 5;
        for (int i = tid; i < NB; i += 256) {
            float4 v = ((const float4*)boxes)[i * NC + c];
            float bw = __fadd_rn(__fsub_rn(v.z, v.x), 1.0f);
            float bh = __fadd_rn(__fsub_rn(v.w, v.y), 1.0f);
            sm.m.box[i] = v;
            sm.m.area[i] = __fmul_rn(bw, bh);
        }
        __syncthreads();

        unsigned* gb = &g_masks16[(size_t)c * NB * 16];
        int tcnt = 0;
        for (int pb = 0; pb < 16; pb++) {
            for (int jb = pb; jb < 16; jb++, tcnt++) {
                if ((tcnt & 7) != w) continue;
                const int p = (pb << 5) + lane;
                const float4 pv = sm.m.box[p];
                const float par = sm.m.area[p];
                unsigned bword = 0, tmask = 0;
                for (int jj = 0; jj < 32; jj++) {
                    int j = (jb << 5) + jj;
                    float4 bv = sm.m.box[j];
                    float baj = sm.m.area[j];
                    float ix1 = fmaxf(pv.x, bv.x);
                    float iy1 = fmaxf(pv.y, bv.y);
                    float ix2 = fminf(pv.z, bv.z);
                    float iy2 = fminf(pv.w, bv.w);
                    float iw = fmaxf(__fadd_rn(__fsub_rn(ix2, ix1), 1.0f), 0.0f);
                    float ih = fmaxf(__fadd_rn(__fsub_rn(iy2, iy1), 1.0f), 0.0f);
                    float inter = __fmul_rn(iw, ih);
                    float uni = __fsub_rn(__fadd_rn(par, baj), inter);
                    float t3 = __fmul_rn(NMS_T, uni);
                    float diff = inter - t3;
                    bool pred = diff > 0.0f;
                    bool near = fabsf(diff) <= 1e-4f * t3;
                    if (__any_sync(FULL, near)) {
                        float q = __fdiv_rn(inter, uni);
                        if (near) pred = (q >= NMS_T);
                    }
                    unsigned word = __ballot_sync(FULL, pred);
                    if (lane == jj) bword = word;
                    tmask |= ((unsigned)pred) << jj;
                }
                gb[(((jb << 5) + lane) << 4) + pb] = bword;     // boxes in jb, pivot-bits pb
                if (jb != pb)
                    gb[(((pb << 5) + lane) << 4) + jb] = tmask; // boxes in pb, j-bits jb (symmetry)
            }
        }
    } else {
        // ---------------- gemm path (identical per-element accumulation order) ----------------
        const int bi = blockIdx.x - NC;
        const int mt = bi >> 5;          // 0..15 (32-row tiles)
        const int ks = bi & 31;          // 0..31
        const int tx = tid & 15, ty = tid >> 4;  // tx: 10 cols, ty: 2 rows
        const int k0 = ks * BKS;

        float acc[2][10];
#pragma unroll
        for (int i = 0; i < 2; i++)
#pragma unroll
            for (int j = 0; j < 10; j++) acc[i][j] = 0.0f;

        for (int kc = 0; kc < BKS; kc += 8) {
            // load A tile 32x8 (one element per thread)
            {
                int m = tid >> 3, kk = tid & 7;
                sm.g.As[kk][m] = A[(mt * 32 + m) * IN_DIM + k0 + kc + kk];
            }
            // load W tile 8x160 (guard n<151)
#pragma unroll
            for (int r = 0; r < 5; r++) {
                int idx = tid + r * 256;
                int kk = idx / BN, n = idx % BN;
                sm.g.Bs[kk][n] = (n < NC) ? W[(k0 + kc + kk) * NC + n] : 0.0f;
            }
            __syncthreads();
#pragma unroll
            for (int kk = 0; kk < 8; kk++) {
                float a[2], b[10];
#pragma unroll
                for (int i = 0; i < 2; i++) a[i] = sm.g.As[kk][ty * 2 + i];
#pragma unroll
                for (int j = 0; j < 10; j++) b[j] = sm.g.Bs[kk][tx * 10 + j];
#pragma unroll
                for (int i = 0; i < 2; i++)
#pragma unroll
                    for (int j = 0; j < 10; j++) acc[i][j] = fmaf(a[i], b[j], acc[i][j]);
            }
            __syncthreads();
        }
#pragma unroll
        for (int i = 0; i < 2; i++) {
            int m = mt * 32 + ty * 2 + i;
#pragma unroll
            for (int j = 0; j < 10; j++) {
                int n = tx * 10 + j;
                g_part[(ks * NB + m) * BN + n] = acc[i][j];
            }
        }
    }
}

// =================== reduce + bias + softmax + exact top-4 ===================
__global__ void __launch_bounds__(256) softmax_kernel(const float* __restrict__ bias,
                                                      float* __restrict__ out)
{
    const int b = blockIdx.x;
    const int t = threadIdx.x;
    __shared__ float sred[256];
    __shared__ int   sidx[256];
    __shared__ int   s_win;

    float d = -INFINITY;
    if (t < NC) {
        float s = 0.0f;
#pragma unroll 8
        for (int ks = 0; ks < KS; ks++) s += g_part[(ks * NB + b) * BN + t];
        d = s + bias[t];
        out[b * NC + t] = d;
    }
    sred[t] = d;
    __syncthreads();
    for (int off = 128; off; off >>= 1) {
        if (t < off) sred[t] = fmaxf(sred[t], sred[t + off]);
        __syncthreads();
    }
    float m = sred[0];
    __syncthreads();

    float e = (t < NC) ? expf(__fsub_rn(d, m)) : 0.0f;
    sred[t] = e;
    __syncthreads();
    for (int off = 128; off; off >>= 1) {
        if (t < off) sred[t] = __fadd_rn(sred[t], sred[t + off]);
        __syncthreads();
    }
    float s = sred[0];
    __syncthreads();

    float sc = -INFINITY;
    if (t < NC) {
        sc = (t == 0) ? 0.0f : __fdiv_rn(e, s);
        g_scores_rm[b * NC + t] = sc;
    }

    // 4 argmax passes: (val desc, cls asc) with exclusion
    bool excl = false;
#pragma unroll
    for (int p = 0; p < 4; p++) {
        sred[t] = excl ? -INFINITY : sc;
        sidx[t] = t;
        __syncthreads();
        for (int off = 128; off; off >>= 1) {
            if (t < off) {
                float ov = sred[t + off]; int oi = sidx[t + off];
                if (ov > sred[t] || (ov == sred[t] && oi < sidx[t])) { sred[t] = ov; sidx[t] = oi; }
            }
            __syncthreads();
        }
        if (t == 0) {
            g_t4val[b * 4 + p] = sred[0];
            g_t4cls[b * 4 + p] = sidx[0];
            s_win = sidx[0];
        }
        __syncthreads();
        if (t == s_win) excl = true;
        __syncthreads();
    }
}

// =================== sequential greedy NMS (single warp, register-resident, retire-first) ===================
__global__ void __launch_bounds__(32, 1) nms_kernel(float* __restrict__ out)
{
    __shared__ short rarg[NB];
    __shared__ __align__(16) float t4v[NB * 4];
    __shared__ __align__(8)  short t4c[NB * 4];
    __shared__ unsigned zb[NB * 5];
    __shared__ short commits[NB];
    __shared__ short marked[NB];
    __shared__ int s_nm;

    const int l = threadIdx.x;
    float v[16];                       // register-resident rmax of owned rows
    unsigned retm = 0, resm = 0;       // per-lane retired / resurrected bitmasks
    unsigned long long vbq = 0xFFFFFFFFFFFFFFFFull;   // 16 x 4-bit top-4 validity

    // ---- init (each lane its own 16 rows) ----
#pragma unroll
    for (int k = 0; k < 16; k++) {
        int r = (l << 4) + k;
        float4 tv = *(const float4*)&g_t4val[r * 4];
        t4v[r * 4 + 0] = tv.x; t4v[r * 4 + 1] = tv.y;
        t4v[r * 4 + 2] = tv.z; t4v[r * 4 + 3] = tv.w;
        int4 tc = *(const int4*)&g_t4cls[r * 4];
        t4c[r * 4 + 0] = (short)tc.x; t4c[r * 4 + 1] = (short)tc.y;
        t4c[r * 4 + 2] = (short)tc.z; t4c[r * 4 + 3] = (short)tc.w;
        v[k] = tv.x;
        rarg[r] = (short)tc.x;
        commits[r] = 0;
#pragma unroll
        for (int q = 0; q < 5; q++) zb[r * 5 + q] = 0;
    }
    if (l == 0) s_nm = 0;
    __syncwarp();

    // ---- plain register argmax (all-lane, branchless; ties -> lowest row) ----
    auto warp_argmax = [&](int& obox, bool& pos) {
        float a0 = fmaxf(v[0], v[1]),   a1 = fmaxf(v[2], v[3]);
        float a2 = fmaxf(v[4], v[5]),   a3 = fmaxf(v[6], v[7]);
        float a4 = fmaxf(v[8], v[9]),   a5 = fmaxf(v[10], v[11]);
        float a6 = fmaxf(v[12], v[13]), a7 = fmaxf(v[14], v[15]);
        float b0 = fmaxf(a0, a1), b1 = fmaxf(a2, a3);
        float b2 = fmaxf(a4, a5), b3 = fmaxf(a6, a7);
        float c0 = fmaxf(b0, b1), c1 = fmaxf(b2, b3);
        float bm = fmaxf(c0, c1);
        unsigned g0 = (v[0]==bm ? 1u:0u) | (v[1]==bm ? 2u:0u) | (v[2]==bm ? 4u:0u) | (v[3]==bm ? 8u:0u);
        unsigned g1 = (v[4]==bm ? 1u:0u) | (v[5]==bm ? 2u:0u) | (v[6]==bm ? 4u:0u) | (v[7]==bm ? 8u:0u);
        unsigned g2 = (v[8]==bm ? 1u:0u) | (v[9]==bm ? 2u:0u) | (v[10]==bm ? 4u:0u) | (v[11]==bm ? 8u:0u);
        unsigned g3 = (v[12]==bm ? 1u:0u) | (v[13]==bm ? 2u:0u) | (v[14]==bm ? 4u:0u) | (v[15]==bm ? 8u:0u);
        unsigned eqm = g0 | (g1 << 4) | (g2 << 8) | (g3 << 12);
        int idx = __ffs(eqm) - 1;
        unsigned m1 = fmono(bm);
        unsigned gm = __reduce_max_sync(FULL, m1);
        unsigned bal = __ballot_sync(FULL, m1 == gm);
        int wl = __ffs(bal) - 1;
        obox = __shfl_sync(FULL, (l << 4) + idx, wl);
        pos = gm > 0x80000000u;        // value strictly > 0
    };

    // ---- branchless hit processing (no v reads; predicated commits) ----
    auto process = [&](unsigned& hits, int cls, int cwi, unsigned cbm) {
        bool has = hits != 0;
        int i = has ? (__ffs(hits) - 1) : 0;
        hits &= hits - 1;
        int r = (l << 4) + i;
        unsigned zw = zb[r * 5 + cwi];
        bool firstz = has && !(zw & cbm);
        bool ret = (retm >> i) & 1u;
        bool res = (resm >> i) & 1u;
        short ra = rarg[r];
        // retired path: new value always 0.0; arg = cls if fresh else min
        bool act_ret = firstz && ret;
        short nra_ret = (!res) ? (short)cls : ((cls < (int)ra) ? (short)cls : ra);
        // live path
        bool livez = firstz && !ret && (cls != 0);
        uint2 cp = *(const uint2*)&t4c[r * 4];
        short c0 = (short)(cp.x & 0xFFFF), c1s = (short)(cp.x >> 16);
        short c2 = (short)(cp.y & 0xFFFF), c3 = (short)(cp.y >> 16);
        int k4 = -1;
        k4 = ((int)c3 == cls) ? 3 : k4;
        k4 = ((int)c2 == cls) ? 2 : k4;
        k4 = ((int)c1s == cls) ? 1 : k4;
        k4 = ((int)c0 == cls) ? 0 : k4;
        unsigned vbm = (unsigned)(vbq >> (i * 4)) & 0xFu;
        bool inv = livez && (k4 >= 0) && ((vbm >> (k4 & 3)) & 1u);
        unsigned vbm2 = vbm & ~(1u << (k4 & 3));
        int h = __ffs(vbm2) - 1; int hh = (h < 0) ? 0 : h;
        float nrm_live = t4v[r * 4 + hh];
        short nra_live = t4c[r * 4 + hh];
        bool promote = inv && (vbm2 != 0);
        bool mark = inv && (vbm2 == 0);
        // predicated commits
        if (act_ret || livez) zb[r * 5 + cwi] = zw | cbm;
        if (act_ret) resm |= 1u << i;
        if (inv) vbq = (vbq & ~(0xFull << (i * 4))) | ((unsigned long long)vbm2 << (i * 4));
        bool wr = act_ret || promote;
        float nv = act_ret ? 0.0f : nrm_live;
        short na = act_ret ? nra_ret : nra_live;
        if (wr) rarg[r] = na;
#pragma unroll
        for (int k = 0; k < 16; k++) v[k] = (wr && k == i) ? nv : v[k];
        if (mark) marked[atomicAdd(&s_nm, 1)] = (short)r;
    };

    // ---- prologue ----
    int box; bool pos0;
    warp_argmax(box, pos0);
    int cls = (int)rarg[box];
    unsigned word = __ldg(&g_masks16[(((size_t)cls * NB) + box) * 16 + (l >> 1)]);

    for (int iter = 0; iter < NB; iter++) {
        if (l == 0) commits[box] = (short)cls;
        const int owner = box >> 4;

        // ---- retire pivot FIRST (owner lane only) ----
        {
            int bi = box & 15;
            bool own = (l == owner);
            if (own) {
                retm |= 1u << bi;
                resm &= ~(1u << bi);
                vbq &= ~(0xFull << (bi * 4));
                rarg[box] = 0;
#pragma unroll
                for (int q = 0; q < 5; q++) zb[box * 5 + q] = 0;
            }
#pragma unroll
            for (int k = 0; k < 16; k++) v[k] = (own && k == bi) ? -1.0f : v[k];
        }

        // ---- exact lookahead: plain argmax (pivot already -1) ----
        int sbox; bool svalid;
        warp_argmax(sbox, svalid);
        int scls = (int)rarg[sbox];
        unsigned sword = __ldg(&g_masks16[(((size_t)scls * NB) + sbox) * 16 + (l >> 1)]);
        unsigned wsb = __shfl_sync(FULL, word, (sbox >> 5) << 1);
        bool sbox_hit = (wsb >> (sbox & 31)) & 1u;

        // ---- update phase ----
        const int cwi = cls >> 5;
        const unsigned cbm = 1u << (cls & 31);
        unsigned hits = (word >> ((l & 1) * 16)) & 0xFFFFu;
        if (l == owner) hits &= ~(1u << (box & 15));
        process(hits, cls, cwi, cbm);                 // peeled common pass
        while (__any_sync(FULL, hits))                // warp-uniform loop
            process(hits, cls, cwi, cbm);
        __syncwarp();

        // ---- rescans (rare): refill top-4 of marked rows ----
        int nm = s_nm;
        if (nm) {
            for (int i = 0; i < nm; i++) {
                int r = (int)marked[i];
                float ev[5];
#pragma unroll
                for (int j = 0; j < 5; j++) {
                    int c = l + 32 * j;
                    float sv = -1e30f;
                    if (c < NC) {
                        sv = __ldg(&g_scores_rm[r * NC + c]);
                        if (c == 0 || ((zb[r * 5 + (c >> 5)] >> (c & 31)) & 1u)) sv = 0.0f;
                    }
                    ev[j] = sv;
                }
                unsigned taken = 0;
                float wv0 = 0.0f; int wc0 = 0;
#pragma unroll
                for (int p = 0; p < 4; p++) {
                    float bv = -1e30f; int bj = -1;
#pragma unroll
                    for (int j = 0; j < 5; j++) {
                        bool can = !((taken >> j) & 1u) && (l + 32 * j < NC);
                        if (can && ev[j] > bv) { bv = ev[j]; bj = j; }
                    }
                    unsigned key = (bj >= 0) ? fmono(bv) : 0u;
                    unsigned gmx = __reduce_max_sync(FULL, key);
                    unsigned candc = (key == gmx && bj >= 0) ? (unsigned)(l + 32 * bj) : 0xFFFFFFFFu;
                    unsigned wc = __reduce_min_sync(FULL, candc);
                    float wv = fmono_inv_u(gmx);
                    if (l == (int)(wc & 31)) taken |= 1u << (wc >> 5);
                    if (l == 0) { t4v[r * 4 + p] = wv; t4c[r * 4 + p] = (short)wc; }
                    if (p == 0) { wv0 = wv; wc0 = (int)wc; }
                }
                if (l == 0) rarg[r] = (short)wc0;
                {
                    int ro = r >> 4, ri = r & 15;
                    bool own = (l == ro);
                    if (own) vbq |= 0xFull << (ri * 4);
#pragma unroll
                    for (int k = 0; k < 16; k++) v[k] = (own && k == ri) ? wv0 : v[k];
                }
            }
            if (l == 0) s_nm = 0;
            __syncwarp();
        }

        // ---- advance (sharpened validity: hit only matters if it demotes sbox's head) ----
        if (svalid && !(sbox_hit && (scls == cls))) {
            box = sbox; cls = scls; word = sword;
        } else {
            bool p2;
            warp_argmax(box, p2);
            cls = (int)rarg[box];
            word = __ldg(&g_masks16[(((size_t)cls * NB) + box) * 16 + (l >> 1)]);
        }
    }

    for (int i = l; i < NB; i += 32) out[NB * NC + i] = (float)commits[i];
}

// =================== launch ===================
extern "C" void kernel_launch(void* const* d_in, const int* in_sizes, int n_in,
                              void* d_out, int out_size) {
    const float* obj_fmap = (const float*)d_in[0];   // [512,4096]
    const float* boxes    = (const float*)d_in[1];   // [512,151,4]
    const float* W        = (const float*)d_in[2];   // [4096,151]
    const float* b        = (const float*)d_in[3];   // [151]
    float* out = (float*)d_out;                      // 77312 dists + 512 preds

    fused_gemm_mask<<<NC + 512, 256>>>(obj_fmap, W, boxes);
    softmax_kernel<<<NB, 256>>>(b, out);
    nms_kernel<<<1, 32>>>(out);
}

// round 17
// speedup vs baseline: 1.3955x; 1.3682x over previous
#include <cuda_runtime.h>
#include <math.h>
#include <stdint.h>

#define NB 512
#define NC 151
#define IN_DIM 4096
#define NMS_T 0.3f
#define FULL 0xffffffffu

#define KS 32            // k-splits
#define BKS (IN_DIM/KS)  // 128
#define BN 160           // padded N

// ---- device scratch (no allocations allowed) ----
__device__ float    g_part[KS * NB * BN];        // split-K partials
__device__ float    g_scores_rm[NB * NC];        // row-major softmax scores
__device__ unsigned g_masks16[NC * NB * 16];     // [c][box][w]: bit l of w = overlap(32w+l, box)
__device__ __align__(16) float g_t4val[NB * 4];  // per-row top-4 values (desc, cls asc)
__device__ int      g_t4cls[NB * 4];

// monotonic-uint mapping for float compare (handles the -1 sentinel)
__device__ __forceinline__ unsigned fmono(float v) {
    unsigned b = __float_as_uint(v);
    return (b & 0x80000000u) ? ~b : (b | 0x80000000u);
}
__device__ __forceinline__ float fmono_inv_u(unsigned u) {
    return (u & 0x80000000u) ? __uint_as_float(u ^ 0x80000000u) : __uint_as_float(~u);
}

// =================== fused: GEMM split-K partials + symmetric IoU masks ===================
__global__ void __launch_bounds__(256) fused_gemm_mask(
    const float* __restrict__ A, const float* __restrict__ W,
    const float* __restrict__ boxes)
{
    __shared__ union {
        struct { float As[8][65]; float Bs[8][BN]; } g;
        struct { float4 box[NB]; float area[NB]; } m;
    } sm;
    const int tid = threadIdx.x;

    if (blockIdx.x < NC) {
        // ---------------- mask path: one class per block, symmetric tiles ----------------
        const int c = blockIdx.x;
        const int lane = tid & 31, w = tid >> 5;
        for (int i = tid; i < NB; i += 256) {
            float4 v = ((const float4*)boxes)[i * NC + c];
            float bw = __fadd_rn(__fsub_rn(v.z, v.x), 1.0f);
            float bh = __fadd_rn(__fsub_rn(v.w, v.y), 1.0f);
            sm.m.box[i] = v;
            sm.m.area[i] = __fmul_rn(bw, bh);
        }
        __syncthreads();

        unsigned* gb = &g_masks16[(size_t)c * NB * 16];
        int tcnt = 0;
        for (int pb = 0; pb < 16; pb++) {
            for (int jb = pb; jb < 16; jb++, tcnt++) {
                if ((tcnt & 7) != w) continue;
                const int p = (pb << 5) + lane;
                const float4 pv = sm.m.box[p];
                const float par = sm.m.area[p];
                unsigned bword = 0, tmask = 0;
                for (int jj = 0; jj < 32; jj++) {
                    int j = (jb << 5) + jj;
                    float4 bv = sm.m.box[j];
                    float baj = sm.m.area[j];
                    float ix1 = fmaxf(pv.x, bv.x);
                    float iy1 = fmaxf(pv.y, bv.y);
                    float ix2 = fminf(pv.z, bv.z);
                    float iy2 = fminf(pv.w, bv.w);
                    float iw = fmaxf(__fadd_rn(__fsub_rn(ix2, ix1), 1.0f), 0.0f);
                    float ih = fmaxf(__fadd_rn(__fsub_rn(iy2, iy1), 1.0f), 0.0f);
                    float inter = __fmul_rn(iw, ih);
                    float uni = __fsub_rn(__fadd_rn(par, baj), inter);
                    float t3 = __fmul_rn(NMS_T, uni);
                    float diff = inter - t3;
                    bool pred = diff > 0.0f;
                    bool near = fabsf(diff) <= 1e-4f * t3;
                    if (__any_sync(FULL, near)) {
                        float q = __fdiv_rn(inter, uni);
                        if (near) pred = (q >= NMS_T);
                    }
                    unsigned word = __ballot_sync(FULL, pred);
                    if (lane == jj) bword = word;
                    tmask |= ((unsigned)pred) << jj;
                }
                gb[(((jb << 5) + lane) << 4) + pb] = bword;     // boxes in jb, pivot-bits pb
                if (jb != pb)
                    gb[(((pb << 5) + lane) << 4) + jb] = tmask; // boxes in pb, j-bits jb (symmetry)
            }
        }
    } else {
        // ---------------- gemm path (identical numerics) ----------------
        const int bi = blockIdx.x - NC;
        const int mt = bi >> 5;          // 0..7
        const int ks = bi & 31;          // 0..31
        const int tx = tid & 15, ty = tid >> 4;
        const int k0 = ks * BKS;

        float acc[4][10];
#pragma unroll
        for (int i = 0; i < 4; i++)
#pragma unroll
            for (int j = 0; j < 10; j++) acc[i][j] = 0.0f;

        for (int kc = 0; kc < BKS; kc += 8) {
#pragma unroll
            for (int r = 0; r < 2; r++) {
                int idx = tid + r * 256;
                int m = idx >> 3, kk = idx & 7;
                sm.g.As[kk][m] = A[(mt * 64 + m) * IN_DIM + k0 + kc + kk];
            }
#pragma unroll
            for (int r = 0; r < 5; r++) {
                int idx = tid + r * 256;
                int kk = idx / BN, n = idx % BN;
                sm.g.Bs[kk][n] = (n < NC) ? W[(k0 + kc + kk) * NC + n] : 0.0f;
            }
            __syncthreads();
#pragma unroll
            for (int kk = 0; kk < 8; kk++) {
                float a[4], b[10];
#pragma unroll
                for (int i = 0; i < 4; i++) a[i] = sm.g.As[kk][ty * 4 + i];
#pragma unroll
                for (int j = 0; j < 10; j++) b[j] = sm.g.Bs[kk][tx * 10 + j];
#pragma unroll
                for (int i = 0; i < 4; i++)
#pragma unroll
                    for (int j = 0; j < 10; j++) acc[i][j] = fmaf(a[i], b[j], acc[i][j]);
            }
            __syncthreads();
        }
#pragma unroll
        for (int i = 0; i < 4; i++) {
            int m = mt * 64 + ty * 4 + i;
#pragma unroll
            for (int j = 0; j < 10; j++) {
                int n = tx * 10 + j;
                g_part[(ks * NB + m) * BN + n] = acc[i][j];
            }
        }
    }
}

// =================== reduce + bias + softmax + exact top-4 ===================
__global__ void __launch_bounds__(256) softmax_kernel(const float* __restrict__ bias,
                                                      float* __restrict__ out)
{
    const int b = blockIdx.x;
    const int t = threadIdx.x;
    __shared__ float sred[256];
    __shared__ int   sidx[256];
    __shared__ int   s_win;

    float d = -INFINITY;
    if (t < NC) {
        float s = 0.0f;
#pragma unroll 8
        for (int ks = 0; ks < KS; ks++) s += g_part[(ks * NB + b) * BN + t];
        d = s + bias[t];
        out[b * NC + t] = d;
    }
    sred[t] = d;
    __syncthreads();
    for (int off = 128; off; off >>= 1) {
        if (t < off) sred[t] = fmaxf(sred[t], sred[t + off]);
        __syncthreads();
    }
    float m = sred[0];
    __syncthreads();

    float e = (t < NC) ? expf(__fsub_rn(d, m)) : 0.0f;
    sred[t] = e;
    __syncthreads();
    for (int off = 128; off; off >>= 1) {
        if (t < off) sred[t] = __fadd_rn(sred[t], sred[t + off]);
        __syncthreads();
    }
    float s = sred[0];
    __syncthreads();

    float sc = -INFINITY;
    if (t < NC) {
        sc = (t == 0) ? 0.0f : __fdiv_rn(e, s);
        g_scores_rm[b * NC + t] = sc;
    }

    // 4 argmax passes: (val desc, cls asc) with exclusion
    bool excl = false;
#pragma unroll
    for (int p = 0; p < 4; p++) {
        sred[t] = excl ? -INFINITY : sc;
        sidx[t] = t;
        __syncthreads();
        for (int off = 128; off; off >>= 1) {
            if (t < off) {
                float ov = sred[t + off]; int oi = sidx[t + off];
                if (ov > sred[t] || (ov == sred[t] && oi < sidx[t])) { sred[t] = ov; sidx[t] = oi; }
            }
            __syncthreads();
        }
        if (t == 0) {
            g_t4val[b * 4 + p] = sred[0];
            g_t4cls[b * 4 + p] = sidx[0];
            s_win = sidx[0];
        }
        __syncthreads();
        if (t == s_win) excl = true;
        __syncthreads();
    }
}

// =================== sequential greedy NMS (single warp, register-resident, retire-first) ===================
__global__ void __launch_bounds__(32, 1) nms_kernel(float* __restrict__ out)
{
    __shared__ short rarg[NB];
    __shared__ __align__(16) float t4v[NB * 4];
    __shared__ __align__(8)  short t4c[NB * 4];
    __shared__ unsigned zb[NB * 5];
    __shared__ short commits[NB];

    const int l = threadIdx.x;
    float v[16];                       // register-resident rmax of owned rows
    unsigned retm = 0, resm = 0;       // per-lane retired / resurrected bitmasks
    unsigned long long vbq = 0xFFFFFFFFFFFFFFFFull;   // 16 x 4-bit top-4 validity
    unsigned mymark = 0;               // per-lane marked-rows bitmask (this iteration)

    // ---- init (each lane its own 16 rows) ----
#pragma unroll
    for (int k = 0; k < 16; k++) {
        int r = (l << 4) + k;
        float4 tv = *(const float4*)&g_t4val[r * 4];
        t4v[r * 4 + 0] = tv.x; t4v[r * 4 + 1] = tv.y;
        t4v[r * 4 + 2] = tv.z; t4v[r * 4 + 3] = tv.w;
        int4 tc = *(const int4*)&g_t4cls[r * 4];
        t4c[r * 4 + 0] = (short)tc.x; t4c[r * 4 + 1] = (short)tc.y;
        t4c[r * 4 + 2] = (short)tc.z; t4c[r * 4 + 3] = (short)tc.w;
        v[k] = tv.x;
        rarg[r] = (short)tc.x;
        commits[r] = 0;
#pragma unroll
        for (int q = 0; q < 5; q++) zb[r * 5 + q] = 0;
    }
    __syncwarp();

    // ---- plain register argmax (all-lane, branchless; ties -> lowest row) ----
    auto warp_argmax = [&](int& obox, bool& pos) {
        float a0 = fmaxf(v[0], v[1]),   a1 = fmaxf(v[2], v[3]);
        float a2 = fmaxf(v[4], v[5]),   a3 = fmaxf(v[6], v[7]);
        float a4 = fmaxf(v[8], v[9]),   a5 = fmaxf(v[10], v[11]);
        float a6 = fmaxf(v[12], v[13]), a7 = fmaxf(v[14], v[15]);
        float b0 = fmaxf(a0, a1), b1 = fmaxf(a2, a3);
        float b2 = fmaxf(a4, a5), b3 = fmaxf(a6, a7);
        float c0 = fmaxf(b0, b1), c1 = fmaxf(b2, b3);
        float bm = fmaxf(c0, c1);
        unsigned g0 = (v[0]==bm ? 1u:0u) | (v[1]==bm ? 2u:0u) | (v[2]==bm ? 4u:0u) | (v[3]==bm ? 8u:0u);
        unsigned g1 = (v[4]==bm ? 1u:0u) | (v[5]==bm ? 2u:0u) | (v[6]==bm ? 4u:0u) | (v[7]==bm ? 8u:0u);
        unsigned g2 = (v[8]==bm ? 1u:0u) | (v[9]==bm ? 2u:0u) | (v[10]==bm ? 4u:0u) | (v[11]==bm ? 8u:0u);
        unsigned g3 = (v[12]==bm ? 1u:0u) | (v[13]==bm ? 2u:0u) | (v[14]==bm ? 4u:0u) | (v[15]==bm ? 8u:0u);
        unsigned eqm = g0 | (g1 << 4) | (g2 << 8) | (g3 << 12);
        int idx = __ffs(eqm) - 1;
        unsigned m1 = fmono(bm);
        unsigned gm = __reduce_max_sync(FULL, m1);
        unsigned bal = __ballot_sync(FULL, m1 == gm);
        int wl = __ffs(bal) - 1;
        obox = __shfl_sync(FULL, (l << 4) + idx, wl);
        pos = gm > 0x80000000u;        // value strictly > 0
    };

    // ---- branchless hit processing (no v reads; predicated commits) ----
    auto process = [&](unsigned& hits, int cls, int cwi, unsigned cbm) {
        bool has = hits != 0;
        int i = has ? (__ffs(hits) - 1) : 0;
        hits &= hits - 1;
        int r = (l << 4) + i;
        unsigned zw = zb[r * 5 + cwi];
        bool firstz = has && !(zw & cbm);
        bool ret = (retm >> i) & 1u;
        bool res = (resm >> i) & 1u;
        short ra = rarg[r];
        // retired path: new value always 0.0; arg = cls if fresh else min
        bool act_ret = firstz && ret;
        short nra_ret = (!res) ? (short)cls : ((cls < (int)ra) ? (short)cls : ra);
        // live path
        bool livez = firstz && !ret && (cls != 0);
        uint2 cp = *(const uint2*)&t4c[r * 4];
        short c0 = (short)(cp.x & 0xFFFF), c1s = (short)(cp.x >> 16);
        short c2 = (short)(cp.y & 0xFFFF), c3 = (short)(cp.y >> 16);
        int k4 = -1;
        k4 = ((int)c3 == cls) ? 3 : k4;
        k4 = ((int)c2 == cls) ? 2 : k4;
        k4 = ((int)c1s == cls) ? 1 : k4;
        k4 = ((int)c0 == cls) ? 0 : k4;
        unsigned vbm = (unsigned)(vbq >> (i * 4)) & 0xFu;
        bool inv = livez && (k4 >= 0) && ((vbm >> (k4 & 3)) & 1u);
        unsigned vbm2 = vbm & ~(1u << (k4 & 3));
        int h = __ffs(vbm2) - 1; int hh = (h < 0) ? 0 : h;
        float nrm_live = t4v[r * 4 + hh];
        short nra_live = t4c[r * 4 + hh];
        bool promote = inv && (vbm2 != 0);
        bool mark = inv && (vbm2 == 0);
        // predicated commits
        if (act_ret || livez) zb[r * 5 + cwi] = zw | cbm;
        if (act_ret) resm |= 1u << i;
        if (inv) vbq = (vbq & ~(0xFull << (i * 4))) | ((unsigned long long)vbm2 << (i * 4));
        bool wr = act_ret || promote;
        float nv = act_ret ? 0.0f : nrm_live;
        short na = act_ret ? nra_ret : nra_live;
        if (wr) rarg[r] = na;
#pragma unroll
        for (int k = 0; k < 16; k++) v[k] = (wr && k == i) ? nv : v[k];
        if (mark) mymark |= 1u << i;
    };

    // ---- prologue ----
    int box; bool pos0;
    warp_argmax(box, pos0);
    int cls = (int)rarg[box];
    unsigned word = __ldg(&g_masks16[(((size_t)cls * NB) + box) * 16 + (l >> 1)]);

    for (int iter = 0; iter < NB; iter++) {
        if (l == 0) commits[box] = (short)cls;
        const int owner = box >> 4;

        // ---- retire pivot FIRST (owner lane only) ----
        {
            int bi = box & 15;
            bool own = (l == owner);
            if (own) {
                retm |= 1u << bi;
                resm &= ~(1u << bi);
                vbq &= ~(0xFull << (bi * 4));
                rarg[box] = 0;
#pragma unroll
                for (int q = 0; q < 5; q++) zb[box * 5 + q] = 0;
            }
#pragma unroll
            for (int k = 0; k < 16; k++) v[k] = (own && k == bi) ? -1.0f : v[k];
        }

        // ---- exact lookahead: plain argmax (pivot already -1) ----
        int sbox; bool svalid;
        warp_argmax(sbox, svalid);
        int scls = (int)rarg[sbox];
        unsigned sword = __ldg(&g_masks16[(((size_t)scls * NB) + sbox) * 16 + (l >> 1)]);
        unsigned wsb = __shfl_sync(FULL, word, (sbox >> 5) << 1);
        bool sbox_hit = (wsb >> (sbox & 31)) & 1u;

        // ---- update phase ----
        const int cwi = cls >> 5;
        const unsigned cbm = 1u << (cls & 31);
        unsigned hits = (word >> ((l & 1) * 16)) & 0xFFFFu;
        if (l == owner) hits &= ~(1u << (box & 15));
        process(hits, cls, cwi, cbm);                 // peeled common pass
        while (__any_sync(FULL, hits))                // warp-uniform loop
            process(hits, cls, cwi, cbm);
        __syncwarp();

        // ---- rescans (rare): ballot-gated, register mark bitmask ----
        unsigned anyb = __ballot_sync(FULL, mymark != 0);
        if (anyb) {
            while (anyb) {
                int lw = __ffs(anyb) - 1;
                anyb &= anyb - 1;
                unsigned mm = __shfl_sync(FULL, mymark, lw);
                while (mm) {
                    int bi = __ffs(mm) - 1; mm &= mm - 1;
                    int r = (lw << 4) + bi;
                    float ev[5];
#pragma unroll
                    for (int j = 0; j < 5; j++) {
                        int c = l + 32 * j;
                        float sv = -1e30f;
                        if (c < NC) {
                            sv = __ldg(&g_scores_rm[r * NC + c]);
                            if (c == 0 || ((zb[r * 5 + (c >> 5)] >> (c & 31)) & 1u)) sv = 0.0f;
                        }
                        ev[j] = sv;
                    }
                    unsigned taken = 0;
                    float wv0 = 0.0f; int wc0 = 0;
#pragma unroll
                    for (int p = 0; p < 4; p++) {
                        float bv = -1e30f; int bj = -1;
#pragma unroll
                        for (int j = 0; j < 5; j++) {
                            bool can = !((taken >> j) & 1u) && (l + 32 * j < NC);
                            if (can && ev[j] > bv) { bv = ev[j]; bj = j; }
                        }
                        unsigned key = (bj >= 0) ? fmono(bv) : 0u;
                        unsigned gmx = __reduce_max_sync(FULL, key);
                        unsigned candc = (key == gmx && bj >= 0) ? (unsigned)(l + 32 * bj) : 0xFFFFFFFFu;
                        unsigned wc = __reduce_min_sync(FULL, candc);
                        float wv = fmono_inv_u(gmx);
                        if (l == (int)(wc & 31)) taken |= 1u << (wc >> 5);
                        if (l == 0) { t4v[r * 4 + p] = wv; t4c[r * 4 + p] = (short)wc; }
                        if (p == 0) { wv0 = wv; wc0 = (int)wc; }
                    }
                    if (l == 0) rarg[r] = (short)wc0;
                    {
                        bool own = (l == lw);
                        if (own) vbq |= 0xFull << (bi * 4);
#pragma unroll
                        for (int k = 0; k < 16; k++) v[k] = (own && k == bi) ? wv0 : v[k];
                    }
                }
            }
            mymark = 0;
            __syncwarp();
        }

        // ---- advance ----
        if (svalid && !sbox_hit) {
            box = sbox; cls = scls; word = sword;
        } else {
            bool p2;
            warp_argmax(box, p2);
            cls = (int)rarg[box];
            word = __ldg(&g_masks16[(((size_t)cls * NB) + box) * 16 + (l >> 1)]);
        }
    }

    for (int i = l; i < NB; i += 32) out[NB * NC + i] = (float)commits[i];
}

// =================== launch ===================
extern "C" void kernel_launch(void* const* d_in, const int* in_sizes, int n_in,
                              void* d_out, int out_size) {
    const float* obj_fmap = (const float*)d_in[0];   // [512,4096]
    const float* boxes    = (const float*)d_in[1];   // [512,151,4]
    const float* W        = (const float*)d_in[2];   // [4096,151]
    const float* b        = (const float*)d_in[3];   // [151]
    float* out = (float*)d_out;                      // 77312 dists + 512 preds

    fused_gemm_mask<<<NC + 256, 256>>>(obj_fmap, W, boxes);
    softmax_kernel<<<NB, 256>>>(b, out);
    nms_kernel<<<1, 32>>>(out);
}